// round 6
// baseline (speedup 1.0000x reference)
#include <cuda_runtime.h>
#include <cstdint>

#define T_ 512
#define H_ 2048
#define F_ 768
#define E_ 64
#define K_ 8
#define KC 16   // K per pipeline stage
#define S_ 3    // pipeline stages

// ---------------- scratch (static __device__, allocation-free) ----------------
__device__ int   g_cnt[E_];
__device__ int   g_off[E_];
__device__ int   g_tok[E_][T_];
__device__ float g_cw [E_][T_];
__device__ float g_h  [(size_t)T_ * K_ * F_];   // 12.6 MB compact slab

// ---------------- helpers ----------------
__device__ __forceinline__ unsigned f2tf(float f) {
    unsigned r; asm("cvt.rna.tf32.f32 %0, %1;" : "=r"(r) : "f"(f)); return r;
}
__device__ __forceinline__ void tfsplit(float v, unsigned& hi, unsigned& lo) {
    hi = f2tf(v);
    lo = f2tf(v - __uint_as_float(hi));
}
__device__ __forceinline__ void mma_tf32(float c[4],
    unsigned a0, unsigned a1, unsigned a2, unsigned a3,
    unsigned b0, unsigned b1) {
    asm volatile(
        "mma.sync.aligned.m16n8k8.row.col.f32.tf32.tf32.f32 "
        "{%0,%1,%2,%3}, {%4,%5,%6,%7}, {%8,%9}, {%0,%1,%2,%3};\n"
        : "+f"(c[0]), "+f"(c[1]), "+f"(c[2]), "+f"(c[3])
        : "r"(a0), "r"(a1), "r"(a2), "r"(a3), "r"(b0), "r"(b1));
}
__device__ __forceinline__ void cp16(void* dst, const void* src) {
    unsigned d = (unsigned)__cvta_generic_to_shared(dst);
    asm volatile("cp.async.cg.shared.global [%0], [%1], 16;\n" :: "r"(d), "l"(src));
}
__device__ __forceinline__ void cp_commit() { asm volatile("cp.async.commit_group;\n"); }
template<int N> __device__ __forceinline__ void cp_wait() {
    asm volatile("cp.async.wait_group %0;\n" :: "n"(N));
}

// ---------------- kernel 0: zero output + counters ----------------
__global__ void k_zero(float* __restrict__ out) {
    int i = blockIdx.x * 256 + threadIdx.x;
    if (i < T_ * H_) out[i] = 0.f;
    if (i < E_) g_cnt[i] = 0;
}

// ---------------- kernel 1: router, 4 tokens/block ----------------
__global__ void k_router(const float* __restrict__ x, const float* __restrict__ gw) {
    __shared__ float sx[4][H_];
    __shared__ float slog[4][E_];
    const int t0 = blockIdx.x * 4;
    const int tid = threadIdx.x;            // 64 threads, one expert each

#pragma unroll
    for (int j = 0; j < 4; j++) {
        const float4* xr = (const float4*)(x + (size_t)(t0 + j) * H_);
        float4* s4 = (float4*)sx[j];
        for (int i = tid; i < H_ / 4; i += 64) s4[i] = xr[i];
    }
    __syncthreads();

    const float4* g4 = (const float4*)(gw + (size_t)tid * H_);
    const float4* s0 = (const float4*)sx[0];
    const float4* s1 = (const float4*)sx[1];
    const float4* s2 = (const float4*)sx[2];
    const float4* s3 = (const float4*)sx[3];
    float a0 = 0.f, a1 = 0.f, a2 = 0.f, a3 = 0.f;
    for (int i = 0; i < H_ / 4; i++) {
        float4 b = g4[i];
        float4 v0 = s0[i]; a0 += v0.x*b.x + v0.y*b.y + v0.z*b.z + v0.w*b.w;
        float4 v1 = s1[i]; a1 += v1.x*b.x + v1.y*b.y + v1.z*b.z + v1.w*b.w;
        float4 v2 = s2[i]; a2 += v2.x*b.x + v2.y*b.y + v2.z*b.z + v2.w*b.w;
        float4 v3 = s3[i]; a3 += v3.x*b.x + v3.y*b.y + v3.z*b.z + v3.w*b.w;
    }
    slog[0][tid] = a0; slog[1][tid] = a1; slog[2][tid] = a2; slog[3][tid] = a3;
    __syncthreads();

    if (tid < 4) {
        const int t = t0 + tid;
        const float* sl = slog[tid];
        int ids[K_]; float lv[K_];
        unsigned long long mask = 0;
        for (int j = 0; j < K_; j++) {
            float best = -1e30f; int bi = 0;
            for (int e = 0; e < E_; e++) {
                if (!((mask >> e) & 1ull) && sl[e] > best) { best = sl[e]; bi = e; }
            }
            mask |= 1ull << bi; ids[j] = bi; lv[j] = best;
        }
        float m = lv[0], s = 0.f, w[K_];
        for (int j = 0; j < K_; j++) { w[j] = __expf(lv[j] - m); s += w[j]; }
        float inv = 1.f / s;
        for (int j = 0; j < K_; j++) {
            int e = ids[j];
            int slot = atomicAdd(&g_cnt[e], 1);
            g_tok[e][slot] = t;
            g_cw [e][slot] = w[j] * inv;
        }
    }
}

// ---------------- kernel 1b: exclusive scan of counts -> slab offsets ----------------
__global__ void k_scan() {
    if (threadIdx.x == 0) {
        int acc = 0;
        for (int e = 0; e < E_; e++) { g_off[e] = acc; acc += g_cnt[e]; }
    }
}

// ---------------- kernel 2: grouped GEMM1 (gate|up fused) + SwiGLU ----------------
// CTA tile M=64 x N=128 (64 gate | 64 up); 8 warps of 32x32.
// cp.async 3-stage pipeline, raw fp32 smem, tf32 split at fragment load.
__global__ __launch_bounds__(256) void k_gemm1(const float* __restrict__ x,
                                               const float* __restrict__ wg,
                                               const float* __restrict__ wu) {
    const int e  = blockIdx.z;
    const int Ne = g_cnt[e];
    const int m0 = blockIdx.y * 64;
    if (m0 >= Ne) return;
    const int n0 = blockIdx.x * 64;

    __shared__ union {
        struct { float A[S_][64][20]; float B[S_][16][136]; } p;  // 41472 B
        float ep[64][132];                                        // epilogue alias
    } sm;

    const int tid  = threadIdx.x;
    const int lane = tid & 31, wid = tid >> 5;
    const int mw = (wid >> 2) * 32;   // 0 / 32
    const int nw = (wid & 3) * 32;    // 0..96

    // A: one 16B chunk / thread / stage
    const int arow = tid >> 2;
    const int aq   = tid & 3;
    const bool avalid = (m0 + arow) < Ne;
    const int tok = avalid ? g_tok[e][m0 + arow] : 0;
    const float* asrc = x + (size_t)tok * H_ + aq * 4;

    // B: two 16B chunks / thread / stage (16 rows x 128 cols: gate 0-63 | up 64-127)
    const int br0 = tid >> 5,          bc0 = tid & 31;
    const int br1 = (tid + 256) >> 5,  bc1 = (tid + 256) & 31;
    const size_t ebase = (size_t)e * H_ * F_;
    const float* bsrc0 = ((bc0 < 16) ? wg : wu) + ebase + (size_t)br0 * F_ + n0 + (bc0 & 15) * 4;
    const float* bsrc1 = ((bc1 < 16) ? wg : wu) + ebase + (size_t)br1 * F_ + n0 + (bc1 & 15) * 4;
    const int bcol0 = (bc0 < 16) ? bc0 * 4 : 64 + (bc0 & 15) * 4;
    const int bcol1 = (bc1 < 16) ? bc1 * 4 : 64 + (bc1 & 15) * 4;

    float acc[2][4][4];
#pragma unroll
    for (int mi = 0; mi < 2; mi++)
#pragma unroll
        for (int ni = 0; ni < 4; ni++)
#pragma unroll
            for (int f = 0; f < 4; f++) acc[mi][ni][f] = 0.f;

    auto issue = [&](int s, int kt) {
        cp16(&sm.p.A[s][arow][aq * 4], asrc + (size_t)kt * KC);
        cp16(&sm.p.B[s][br0][bcol0],   bsrc0 + (size_t)kt * KC * F_);
        cp16(&sm.p.B[s][br1][bcol1],   bsrc1 + (size_t)kt * KC * F_);
        cp_commit();
    };

    auto compute = [&](int buf) {
#pragma unroll
        for (int ks = 0; ks < 2; ks++) {
            unsigned ah[2][4], al[2][4], b[4][2];
#pragma unroll
            for (int mi = 0; mi < 2; mi++) {
                const int r = mw + mi * 16 + (lane >> 2);
                const int c = ks * 8 + (lane & 3);
                tfsplit(sm.p.A[buf][r    ][c    ], ah[mi][0], al[mi][0]);
                tfsplit(sm.p.A[buf][r + 8][c    ], ah[mi][1], al[mi][1]);
                tfsplit(sm.p.A[buf][r    ][c + 4], ah[mi][2], al[mi][2]);
                tfsplit(sm.p.A[buf][r + 8][c + 4], ah[mi][3], al[mi][3]);
            }
#pragma unroll
            for (int ni = 0; ni < 4; ni++) {
                const int cc = nw + ni * 8 + (lane >> 2);
                const int rr = ks * 8 + (lane & 3);
                b[ni][0] = f2tf(sm.p.B[buf][rr    ][cc]);
                b[ni][1] = f2tf(sm.p.B[buf][rr + 4][cc]);
            }
#pragma unroll
            for (int mi = 0; mi < 2; mi++)
#pragma unroll
                for (int ni = 0; ni < 4; ni++) {
                    mma_tf32(acc[mi][ni], ah[mi][0], ah[mi][1], ah[mi][2], ah[mi][3],
                             b[ni][0], b[ni][1]);
                    mma_tf32(acc[mi][ni], al[mi][0], al[mi][1], al[mi][2], al[mi][3],
                             b[ni][0], b[ni][1]);
                }
        }
    };

    const int NK = H_ / KC;   // 128
#pragma unroll
    for (int s = 0; s < S_ - 1; s++) issue(s, s);
    for (int kt = 0; kt < NK; kt++) {
        if (kt + S_ - 1 < NK) {
            cp_wait<S_ - 2>();          // stage kt%S_ resident (<= S_-2 groups pending)
            __syncthreads();
            issue((kt + S_ - 1) % S_, kt + S_ - 1);
        } else {
            cp_wait<0>();               // tail drain
            __syncthreads();
        }
        compute(kt % S_);
    }
    __syncthreads();

    // epilogue: exchange gate/up via smem, SwiGLU * combine weight -> g_h
#pragma unroll
    for (int mi = 0; mi < 2; mi++)
#pragma unroll
        for (int ni = 0; ni < 4; ni++)
#pragma unroll
            for (int f = 0; f < 4; f++) {
                int r = mw + mi * 16 + (lane >> 2) + ((f >= 2) ? 8 : 0);
                int c = nw + ni * 8 + (lane & 3) * 2 + (f & 1);
                sm.ep[r][c] = acc[mi][ni][f];
            }
    __syncthreads();

    float* hout = g_h + ((size_t)(g_off[e] + m0)) * F_ + n0;
    for (int i = tid; i < 64 * 64; i += 256) {
        int m = i >> 6, n = i & 63;
        if (m0 + m < Ne) {
            float g = sm.ep[m][n], u = sm.ep[m][64 + n];
            float sg = g / (1.f + __expf(-g));
            hout[(size_t)m * F_ + n] = sg * u * g_cw[e][m0 + m];
        }
    }
}

// ---------------- kernel 3: grouped GEMM2 (h @ w_down), atomic combine ----------------
// CTA tile M=64 x N=128, K=768; cp.async pipeline, split at fragment load.
__global__ __launch_bounds__(256) void k_gemm2(const float* __restrict__ wd,
                                               float* __restrict__ out) {
    const int e  = blockIdx.z;
    const int Ne = g_cnt[e];
    const int m0 = blockIdx.y * 64;
    if (m0 >= Ne) return;
    const int n0 = blockIdx.x * 128;

    __shared__ struct { float A[S_][64][20]; float B[S_][16][136]; } sm;

    const int tid  = threadIdx.x;
    const int lane = tid & 31, wid = tid >> 5;
    const int mw = (wid >> 2) * 32;
    const int nw = (wid & 3) * 32;

    const int arow = tid >> 2;
    const int aq   = tid & 3;
    const bool avalid = (m0 + arow) < Ne;
    const int hr = g_off[e] + (avalid ? (m0 + arow) : 0);
    const float* asrc = g_h + (size_t)hr * F_ + aq * 4;

    const int br0 = tid >> 5,          bc0 = tid & 31;
    const int br1 = (tid + 256) >> 5,  bc1 = (tid + 256) & 31;
    const float* wdB = wd + (size_t)e * F_ * H_ + n0;
    const float* bsrc0 = wdB + (size_t)br0 * H_ + bc0 * 4;
    const float* bsrc1 = wdB + (size_t)br1 * H_ + bc1 * 4;

    float acc[2][4][4];
#pragma unroll
    for (int mi = 0; mi < 2; mi++)
#pragma unroll
        for (int ni = 0; ni < 4; ni++)
#pragma unroll
            for (int f = 0; f < 4; f++) acc[mi][ni][f] = 0.f;

    auto issue = [&](int s, int kt) {
        cp16(&sm.A[s][arow][aq * 4], asrc + (size_t)kt * KC);
        cp16(&sm.B[s][br0][bc0 * 4], bsrc0 + (size_t)kt * KC * H_);
        cp16(&sm.B[s][br1][bc1 * 4], bsrc1 + (size_t)kt * KC * H_);
        cp_commit();
    };

    auto compute = [&](int buf) {
#pragma unroll
        for (int ks = 0; ks < 2; ks++) {
            unsigned ah[2][4], al[2][4], b[4][2];
#pragma unroll
            for (int mi = 0; mi < 2; mi++) {
                const int r = mw + mi * 16 + (lane >> 2);
                const int c = ks * 8 + (lane & 3);
                tfsplit(sm.A[buf][r    ][c    ], ah[mi][0], al[mi][0]);
                tfsplit(sm.A[buf][r + 8][c    ], ah[mi][1], al[mi][1]);
                tfsplit(sm.A[buf][r    ][c + 4], ah[mi][2], al[mi][2]);
                tfsplit(sm.A[buf][r + 8][c + 4], ah[mi][3], al[mi][3]);
            }
#pragma unroll
            for (int ni = 0; ni < 4; ni++) {
                const int cc = nw + ni * 8 + (lane >> 2);
                const int rr = ks * 8 + (lane & 3);
                b[ni][0] = f2tf(sm.B[buf][rr    ][cc]);
                b[ni][1] = f2tf(sm.B[buf][rr + 4][cc]);
            }
#pragma unroll
            for (int mi = 0; mi < 2; mi++)
#pragma unroll
                for (int ni = 0; ni < 4; ni++) {
                    mma_tf32(acc[mi][ni], ah[mi][0], ah[mi][1], ah[mi][2], ah[mi][3],
                             b[ni][0], b[ni][1]);
                    mma_tf32(acc[mi][ni], al[mi][0], al[mi][1], al[mi][2], al[mi][3],
                             b[ni][0], b[ni][1]);
                }
        }
    };

    const int NK = F_ / KC;   // 48
#pragma unroll
    for (int s = 0; s < S_ - 1; s++) issue(s, s);
    for (int kt = 0; kt < NK; kt++) {
        if (kt + S_ - 1 < NK) {
            cp_wait<S_ - 2>();
            __syncthreads();
            issue((kt + S_ - 1) % S_, kt + S_ - 1);
        } else {
            cp_wait<0>();
            __syncthreads();
        }
        compute(kt % S_);
    }

    // epilogue: atomic accumulate into out rows (token per M-row)
    int toks[2][2];
#pragma unroll
    for (int mi = 0; mi < 2; mi++)
#pragma unroll
        for (int ro = 0; ro < 2; ro++) {
            int r = m0 + mw + mi * 16 + (lane >> 2) + ro * 8;
            toks[mi][ro] = (r < Ne) ? g_tok[e][r] : -1;
        }
#pragma unroll
    for (int mi = 0; mi < 2; mi++)
#pragma unroll
        for (int ni = 0; ni < 4; ni++)
#pragma unroll
            for (int f = 0; f < 4; f++) {
                int tok = toks[mi][f >> 1];
                if (tok >= 0) {
                    int c = n0 + nw + ni * 8 + (lane & 3) * 2 + (f & 1);
                    atomicAdd(&out[(size_t)tok * H_ + c], acc[mi][ni][f]);
                }
            }
}

// ---------------- launch ----------------
extern "C" void kernel_launch(void* const* d_in, const int* in_sizes, int n_in,
                              void* d_out, int out_size) {
    const float* x     = (const float*)d_in[0];
    const float* gw    = (const float*)d_in[1];
    const float* wgate = (const float*)d_in[2];
    const float* wup   = (const float*)d_in[3];
    const float* wdown = (const float*)d_in[4];
    float* out = (float*)d_out;

    k_zero<<<(T_ * H_ + 255) / 256, 256>>>(out);
    k_router<<<T_ / 4, 64>>>(x, gw);
    k_scan<<<1, 32>>>();
    k_gemm1<<<dim3(F_ / 64, T_ / 64, E_), 256>>>(x, wgate, wup);
    k_gemm2<<<dim3(H_ / 128, T_ / 64, E_), 256>>>(wdown, out);
}